// round 16
// baseline (speedup 1.0000x reference)
#include <cuda_runtime.h>
#include <cuda_bf16.h>
#include <math.h>
#include <stdint.h>

#define BATCH 8
#define CC 512
#define NN 4096
#define GG 32
#define CPG 16
#define MT 4

// ---- scratch (static device globals; allowed by harness rules) ----
__device__ __nv_bfloat16 g_qt[(size_t)BATCH * NN * CC];    // q_t  [b][n][c]
__device__ __nv_bfloat16 g_ktb[(size_t)BATCH * NN * CC];   // k_t  [b][m][c]
__device__ __nv_bfloat16 g_kb[(size_t)BATCH * CC * NN];    // k    [b][c][m]
__device__ __nv_bfloat16 g_xt[(size_t)BATCH * NN * CC];    // x_t  [b][n][c]
__device__ __nv_bfloat16 g_attt[(size_t)BATCH * NN * CC];  // att_t[b][n][c]
__device__ __nv_bfloat16 g_s[(size_t)BATCH * NN * NN];     // E = exp(S) [b][n][m]
__device__ float g_psum[(size_t)BATCH * NN * 32];          // per-mblock row partials
__device__ float g_rowsum[(size_t)BATCH * NN];             // sum_m exp(S)
__device__ __nv_bfloat16 g_qwf[(size_t)BATCH * CC * CC];
__device__ __nv_bfloat16 g_kwf[(size_t)BATCH * CC * CC];
__device__ __nv_bfloat16 g_pwf[(size_t)CC * CC];
__device__ float g_stats[BATCH * GG * 2];
__device__ float g_qbf[BATCH * CC];
__device__ float g_kbf[BATCH * CC];

// ============================================================
// helpers
// ============================================================
__device__ __forceinline__ unsigned packbf(float x, float y) {
    __nv_bfloat162 h = __float22bfloat162_rn(make_float2(x, y));
    return *reinterpret_cast<unsigned*>(&h);
}

__device__ __forceinline__ void mma16(float* c, unsigned a0, unsigned a1, unsigned a2, unsigned a3,
                                      unsigned b0, unsigned b1) {
    asm volatile(
        "mma.sync.aligned.m16n8k16.row.col.f32.bf16.bf16.f32 "
        "{%0,%1,%2,%3},{%4,%5,%6,%7},{%8,%9},{%0,%1,%2,%3};"
        : "+f"(c[0]), "+f"(c[1]), "+f"(c[2]), "+f"(c[3])
        : "r"(a0), "r"(a1), "r"(a2), "r"(a3), "r"(b0), "r"(b1));
}

#define LDSM4(r0, r1, r2, r3, addr) \
    asm volatile("ldmatrix.sync.aligned.m8n8.x4.shared.b16 {%0,%1,%2,%3}, [%4];" \
                 : "=r"(r0), "=r"(r1), "=r"(r2), "=r"(r3) : "r"(addr))

__device__ __forceinline__ void cp16(void* smem_dst, const void* gsrc) {
    unsigned s = (unsigned)__cvta_generic_to_shared(smem_dst);
    asm volatile("cp.async.cg.shared.global [%0], [%1], 16;" :: "r"(s), "l"(gsrc));
}
#define CP_COMMIT asm volatile("cp.async.commit_group;")
#define CP_WAIT1 asm volatile("cp.async.wait_group 1;")
#define CP_WAIT0 asm volatile("cp.async.wait_group 0;")

__device__ __forceinline__ uint32_t smem_u32(const void* p) {
    uint32_t a;
    asm("{ .reg .u64 t; cvta.to.shared.u64 t, %1; cvt.u32.u64 %0, t; }" : "=r"(a) : "l"(p));
    return a;
}

// ============================================================
// bf16 GEMM mainloop (128x128 tile, 8 warps 64x32, 2-stage).
// smem stage s at s*36864: A [128][72 bf16] (144 B pitch), B at +18432.
// ============================================================
#define STAGE_B 36864
#define SMEM_DYN (2 * STAGE_B)

__device__ __forceinline__ void bf_gemm(const __nv_bfloat16* A, size_t ldA,
                                        const __nv_bfloat16* B, size_t ldB,
                                        int NCH, char* sdyn, uint32_t sbase,
                                        float acc[4][4][4]) {
    int tid = threadIdx.x, lane = tid & 31, wid = tid >> 5;
    int wm = (wid & 1) * 64, wn = (wid >> 1) * 32;
    int lrow = tid >> 3, lseg = tid & 7;

    uint32_t a_off = (uint32_t)(((lane & 7) + ((lane >> 3) & 1) * 8) * 144 + (lane >> 4) * 16);
    uint32_t b_off = (uint32_t)((((lane >> 4) << 3) + (lane & 7)) * 144 + ((lane >> 3) & 1) * 16);

#define BF_LOAD(st, c0)                                                                   \
    {                                                                                     \
        _Pragma("unroll") for (int r = 0; r < 4; r++) {                                   \
            int rr = lrow + r * 32;                                                       \
            cp16(sdyn + (st) * STAGE_B + rr * 144 + lseg * 16,                            \
                 A + (size_t)rr * ldA + (c0) + lseg * 8);                                 \
            cp16(sdyn + (st) * STAGE_B + 18432 + rr * 144 + lseg * 16,                    \
                 B + (size_t)rr * ldB + (c0) + lseg * 8);                                 \
        }                                                                                 \
    }

    BF_LOAD(0, 0);
    CP_COMMIT;
    for (int it = 0; it < NCH; it++) {
        if (it + 1 < NCH) {
            BF_LOAD((it + 1) & 1, (it + 1) * 64);
            CP_COMMIT;
            CP_WAIT1;
        } else {
            CP_WAIT0;
        }
        __syncthreads();
        uint32_t sA = sbase + (it & 1) * STAGE_B + wm * 144;
        uint32_t sB = sbase + (it & 1) * STAGE_B + 18432 + wn * 144;
#pragma unroll
        for (int ks = 0; ks < 4; ks++) {
            unsigned a[4][4], bb[2][4];
#pragma unroll
            for (int mi = 0; mi < 4; mi++)
                LDSM4(a[mi][0], a[mi][1], a[mi][2], a[mi][3],
                      sA + mi * (16 * 144) + ks * 32 + a_off);
#pragma unroll
            for (int np = 0; np < 2; np++)
                LDSM4(bb[np][0], bb[np][1], bb[np][2], bb[np][3],
                      sB + np * (16 * 144) + ks * 32 + b_off);
#pragma unroll
            for (int mi = 0; mi < 4; mi++) {
                mma16(acc[mi][0], a[mi][0], a[mi][1], a[mi][2], a[mi][3], bb[0][0], bb[0][1]);
                mma16(acc[mi][1], a[mi][0], a[mi][1], a[mi][2], a[mi][3], bb[0][2], bb[0][3]);
                mma16(acc[mi][2], a[mi][0], a[mi][1], a[mi][2], a[mi][3], bb[1][0], bb[1][1]);
                mma16(acc[mi][3], a[mi][0], a[mi][1], a[mi][2], a[mi][3], bb[1][2], bb[1][3]);
            }
        }
        __syncthreads();
    }
#undef BF_LOAD
}

// ============================================================
// Kernel 1: GroupNorm statistics (float4 loads)
// ============================================================
__global__ void gn_stats_kernel(const float* __restrict__ x) {
    int b = blockIdx.x, g = blockIdx.y;
    const float4* xp = (const float4*)(x + ((size_t)(b * CC) + g * CPG) * NN);
    float s = 0.f, s2 = 0.f;
    for (int i = threadIdx.x; i < CPG * NN / 4; i += 256) {
        float4 v = xp[i];
        s += v.x + v.y + v.z + v.w;
        s2 += v.x * v.x + v.y * v.y + v.z * v.z + v.w * v.w;
    }
    __shared__ float sh[256], sh2[256];
    sh[threadIdx.x] = s;
    sh2[threadIdx.x] = s2;
    __syncthreads();
    for (int off = 128; off > 0; off >>= 1) {
        if (threadIdx.x < off) {
            sh[threadIdx.x] += sh[threadIdx.x + off];
            sh2[threadIdx.x] += sh2[threadIdx.x + off];
        }
        __syncthreads();
    }
    if (threadIdx.x == 0) {
        const float inv = 1.f / (float)(CPG * NN);
        float mu = sh[0] * inv;
        float var = sh2[0] * inv - mu * mu;
        g_stats[(b * GG + g) * 2 + 0] = mu;
        g_stats[(b * GG + g) * 2 + 1] = rsqrtf(var + 1e-6f);
    }
}

// ============================================================
// Kernel 2: fold GN + softmax scale into bf16 weights + fp32 biases
// ============================================================
__global__ void fold_kernel(const float* __restrict__ qw, const float* __restrict__ qb,
                            const float* __restrict__ kw, const float* __restrict__ kb,
                            const float* __restrict__ pw,
                            const float* __restrict__ gamma, const float* __restrict__ beta) {
    int b = blockIdx.x, o0 = blockIdx.y * 128;
    __shared__ float ga[CC], be[CC];
    for (int c = threadIdx.x; c < CC; c += 256) {
        int g = c >> 4;
        float mu = g_stats[(b * GG + g) * 2 + 0];
        float rstd = g_stats[(b * GG + g) * 2 + 1];
        float gg = gamma[c] * rstd;
        ga[c] = gg;
        be[c] = beta[c] - mu * gg;
    }
    __syncthreads();
    const float s = rsqrtf((float)CC);
    for (int idx = threadIdx.x; idx < 128 * CC; idx += 256) {
        int o = o0 + (idx >> 9), c = idx & (CC - 1);
        g_qwf[((size_t)b * CC + o) * CC + c] = __float2bfloat16_rn(qw[(size_t)o * CC + c] * ga[c] * s);
        g_kwf[((size_t)b * CC + o) * CC + c] = __float2bfloat16_rn(kw[(size_t)o * CC + c] * ga[c]);
    }
    {
        int o = o0 + (threadIdx.x >> 1);
        int h = (threadIdx.x & 1) * 256;
        float sq = 0.f, sk = 0.f;
        for (int c = h; c < h + 256; c++) {
            sq += qw[(size_t)o * CC + c] * be[c];
            sk += kw[(size_t)o * CC + c] * be[c];
        }
        sq += __shfl_xor_sync(0xffffffffu, sq, 1);
        sk += __shfl_xor_sync(0xffffffffu, sk, 1);
        if ((threadIdx.x & 1) == 0) {
            g_qbf[b * CC + o] = (qb[o] + sq) * s;
            g_kbf[b * CC + o] = kb[o] + sk;
        }
    }
    if (b == 0) {
        for (int idx = threadIdx.x; idx < 128 * CC; idx += 256) {
            int o = o0 + (idx >> 9), c = idx & (CC - 1);
            g_pwf[(size_t)o * CC + c] = __float2bfloat16_rn(pw[(size_t)o * CC + c]);
        }
    }
}

// ============================================================
// Kernel 3: x[c][n] fp32 -> x_t[n][c] bf16, 64x64 tiles, vectorized.
// ============================================================
__global__ void xt_kernel(const float* __restrict__ x) {
    __shared__ float ts[64][68];
    int b = blockIdx.z;
    int n0 = blockIdx.x * 64, c0 = blockIdx.y * 64;
    int tid = threadIdx.x;
    {
        int cl = tid >> 4;
        int n4 = (tid & 15) * 4;
#pragma unroll
        for (int r = 0; r < 4; r++) {
            int c = cl + r * 16;
            float4 v = *(const float4*)(x + ((size_t)b * CC + c0 + c) * NN + n0 + n4);
            ts[c][n4] = v.x;
            ts[c][n4 + 1] = v.y;
            ts[c][n4 + 2] = v.z;
            ts[c][n4 + 3] = v.w;
        }
    }
    __syncthreads();
    {
        int nl = tid >> 3;
        int c8 = (tid & 7) * 8;
#pragma unroll
        for (int r = 0; r < 2; r++) {
            int n = nl + r * 32;
            unsigned u[4];
#pragma unroll
            for (int j = 0; j < 4; j++)
                u[j] = packbf(ts[c8 + 2 * j][n], ts[c8 + 2 * j + 1][n]);
            uint4 o = make_uint4(u[0], u[1], u[2], u[3]);
            *(uint4*)&g_xt[((size_t)b * NN + n0 + n) * CC + c0 + c8] = o;
        }
    }
}

// ============================================================
// Kernel 4: q/k projection + transposed epilogues.
// ============================================================
__global__ __launch_bounds__(256, 2) void qk_bf_kernel() {
    extern __shared__ char sdyn[];
    uint32_t sbase = smem_u32(sdyn);
    int b = blockIdx.z >> 1, which = blockIdx.z & 1;
    int o_blk = blockIdx.y * 128, n_blk = blockIdx.x * 128;
    const __nv_bfloat16* A = (which ? g_kwf : g_qwf) + (size_t)b * CC * CC + (size_t)o_blk * CC;
    const __nv_bfloat16* B = g_xt + (size_t)b * NN * CC + (size_t)n_blk * CC;
    const float* bias = (which ? g_kbf : g_qbf) + b * CC;

    float acc[4][4][4] = {};
    bf_gemm(A, CC, B, CC, CC / 64, sdyn, sbase, acc);

    int tid = threadIdx.x, lane = tid & 31, wid = tid >> 5;
    int gid = lane >> 2, tig = lane & 3;
    int wm = (wid & 1) * 64, wn = (wid >> 1) * 32;

    __nv_bfloat16* T = (__nv_bfloat16*)sdyn;  // [128 n][136 o-pitch]
#pragma unroll
    for (int mi = 0; mi < 4; mi++) {
        int ol = wm + mi * 16 + gid;
        float bv0 = bias[o_blk + ol], bv1 = bias[o_blk + ol + 8];
#pragma unroll
        for (int ni = 0; ni < 4; ni++) {
            int nl = wn + ni * 8 + tig * 2;
            __nv_bfloat16 b00 = __float2bfloat16_rn(acc[mi][ni][0] + bv0);
            __nv_bfloat16 b01 = __float2bfloat16_rn(acc[mi][ni][1] + bv0);
            __nv_bfloat16 b10 = __float2bfloat16_rn(acc[mi][ni][2] + bv1);
            __nv_bfloat16 b11 = __float2bfloat16_rn(acc[mi][ni][3] + bv1);
            if (which) {
                __nv_bfloat162 p0; p0.x = b00; p0.y = b01;
                __nv_bfloat162 p1; p1.x = b10; p1.y = b11;
                *(__nv_bfloat162*)&g_kb[((size_t)b * CC + o_blk + ol) * NN + n_blk + nl] = p0;
                *(__nv_bfloat162*)&g_kb[((size_t)b * CC + o_blk + ol + 8) * NN + n_blk + nl] = p1;
            }
            T[nl * 136 + ol] = b00;
            T[(nl + 1) * 136 + ol] = b01;
            T[nl * 136 + ol + 8] = b10;
            T[(nl + 1) * 136 + ol + 8] = b11;
        }
    }
    __syncthreads();
    {
        __nv_bfloat16* dst = (which ? g_ktb : g_qt) + (size_t)b * NN * CC;
        int nl = tid >> 1, h = tid & 1;
        __nv_bfloat16* drow = dst + (size_t)(n_blk + nl) * CC + o_blk + h * 64;
        const __nv_bfloat16* srow = T + nl * 136 + h * 64;
#pragma unroll
        for (int j = 0; j < 8; j++)
            *(uint4*)(drow + j * 8) = *(const uint4*)(srow + j * 8);
    }
}

// ============================================================
// Kernel 5: scores, MULTI-TILE (MT m-tiles per CTA, continuous pipeline)
// + fused exp + row partial sums (smem atomics -> g_psum).
// ============================================================
__global__ __launch_bounds__(256, 2) void scores_bf_kernel() {
    extern __shared__ char sdyn[];
    __shared__ float srow[128];
    uint32_t sbase = smem_u32(sdyn);
    int b = blockIdx.z;
    int nB = blockIdx.y * 128;
    int mB0 = blockIdx.x * (128 * MT);
    const __nv_bfloat16* A = g_qt + (size_t)b * NN * CC + (size_t)nB * CC;
    const __nv_bfloat16* Bk = g_ktb + (size_t)b * NN * CC + (size_t)mB0 * CC;

    int tid = threadIdx.x, lane = tid & 31, wid = tid >> 5;
    int wm = (wid & 1) * 64, wn = (wid >> 1) * 32;
    int lrow = tid >> 3, lseg = tid & 7;
    int gid = lane >> 2, tig = lane & 3;

    uint32_t a_off = (uint32_t)(((lane & 7) + ((lane >> 3) & 1) * 8) * 144 + (lane >> 4) * 16);
    uint32_t b_off = (uint32_t)((((lane >> 4) << 3) + (lane & 7)) * 144 + ((lane >> 3) & 1) * 16);

    if (tid < 128) srow[tid] = 0.f;
    float acc[4][4][4] = {};

    const int NCH = CC / 64;        // 8 chunks per tile
    const int G = MT * NCH;         // 32 flattened chunks

#define SC_LOAD(g)                                                                        \
    {                                                                                     \
        int t_ = (g) >> 3, c0_ = ((g) & 7) * 64, st_ = (g) & 1;                           \
        const __nv_bfloat16* Bt_ = Bk + (size_t)(t_ * 128) * CC;                          \
        _Pragma("unroll") for (int r = 0; r < 4; r++) {                                   \
            int rr = lrow + r * 32;                                                       \
            cp16(sdyn + st_ * STAGE_B + rr * 144 + lseg * 16,                             \
                 A + (size_t)rr * CC + c0_ + lseg * 8);                                   \
            cp16(sdyn + st_ * STAGE_B + 18432 + rr * 144 + lseg * 16,                     \
                 Bt_ + (size_t)rr * CC + c0_ + lseg * 8);                                 \
        }                                                                                 \
    }

    SC_LOAD(0);
    CP_COMMIT;
    for (int g = 0; g < G; g++) {
        if (g + 1 < G) {
            SC_LOAD(g + 1);
            CP_COMMIT;
            CP_WAIT1;
        } else {
            CP_WAIT0;
        }
        __syncthreads();
        uint32_t sA = sbase + (g & 1) * STAGE_B + wm * 144;
        uint32_t sB = sbase + (g & 1) * STAGE_B + 18432 + wn * 144;
#pragma unroll
        for (int ks = 0; ks < 4; ks++) {
            unsigned a[4][4], bb[2][4];
#pragma unroll
            for (int mi = 0; mi < 4; mi++)
                LDSM4(a[mi][0], a[mi][1], a[mi][2], a[mi][3],
                      sA + mi * (16 * 144) + ks * 32 + a_off);
#pragma unroll
            for (int np = 0; np < 2; np++)
                LDSM4(bb[np][0], bb[np][1], bb[np][2], bb[np][3],
                      sB + np * (16 * 144) + ks * 32 + b_off);
#pragma unroll
            for (int mi = 0; mi < 4; mi++) {
                mma16(acc[mi][0], a[mi][0], a[mi][1], a[mi][2], a[mi][3], bb[0][0], bb[0][1]);
                mma16(acc[mi][1], a[mi][0], a[mi][1], a[mi][2], a[mi][3], bb[0][2], bb[0][3]);
                mma16(acc[mi][2], a[mi][0], a[mi][1], a[mi][2], a[mi][3], bb[1][0], bb[1][1]);
                mma16(acc[mi][3], a[mi][0], a[mi][1], a[mi][2], a[mi][3], bb[1][2], bb[1][3]);
            }
        }
        if ((g & 7) == 7) {
            // epilogue for tile t (loads for t+1 already in flight)
            int t = g >> 3;
            int mB = mB0 + t * 128;
#pragma unroll
            for (int mi = 0; mi < 4; mi++) {
                int rloc = wm + mi * 16 + gid;
                int qrow = nB + rloc;
                __nv_bfloat16* p0 = g_s + ((size_t)b * NN + qrow) * NN + mB;
                __nv_bfloat16* p1 = p0 + (size_t)8 * NN;
                float s0 = 0.f, s1 = 0.f;
#pragma unroll
                for (int ni = 0; ni < 4; ni++) {
                    int cb = wn + ni * 8 + tig * 2;
                    float e0 = __expf(acc[mi][ni][0]);
                    float e1 = __expf(acc[mi][ni][1]);
                    float e2 = __expf(acc[mi][ni][2]);
                    float e3 = __expf(acc[mi][ni][3]);
                    s0 += e0 + e1;
                    s1 += e2 + e3;
                    *(unsigned*)(p0 + cb) = packbf(e0, e1);
                    *(unsigned*)(p1 + cb) = packbf(e2, e3);
                    acc[mi][ni][0] = 0.f;
                    acc[mi][ni][1] = 0.f;
                    acc[mi][ni][2] = 0.f;
                    acc[mi][ni][3] = 0.f;
                }
                s0 += __shfl_xor_sync(0xffffffffu, s0, 1);
                s0 += __shfl_xor_sync(0xffffffffu, s0, 2);
                s1 += __shfl_xor_sync(0xffffffffu, s1, 1);
                s1 += __shfl_xor_sync(0xffffffffu, s1, 2);
                if (tig == 0) {
                    atomicAdd(&srow[rloc], s0);
                    atomicAdd(&srow[rloc + 8], s1);
                }
            }
            __syncthreads();
            if (tid < 128) {
                g_psum[((size_t)b * NN + nB + tid) * 32 + blockIdx.x * MT + t] = srow[tid];
                srow[tid] = 0.f;
            }
        }
        __syncthreads();
    }
#undef SC_LOAD
}

// ============================================================
// Kernel 6: rowsum reduce. g_rowsum[row] = sum of 32 partials.
// ============================================================
__global__ void rowsum_reduce_kernel() {
    size_t row = (size_t)blockIdx.x * 256 + threadIdx.x;
    const float* p = g_psum + row * 32;
    float s = 0.f;
#pragma unroll
    for (int i = 0; i < 32; i++) s += p[i];
    g_rowsum[row] = s;
}

// ============================================================
// Kernel 7: AV + normalization. att_t[n][c] = (k·E^T)[c][n] / rowsum[n]
// ============================================================
__global__ __launch_bounds__(256, 2) void av_bf_kernel() {
    extern __shared__ char sdyn[];
    uint32_t sbase = smem_u32(sdyn);
    int b = blockIdx.z;
    int cB = blockIdx.y * 128, nB = blockIdx.x * 128;
    const __nv_bfloat16* A = g_kb + (size_t)b * CC * NN + (size_t)cB * NN;
    const __nv_bfloat16* B = g_s + (size_t)b * NN * NN + (size_t)nB * NN;

    float acc[4][4][4] = {};
    bf_gemm(A, NN, B, NN, NN / 64, sdyn, sbase, acc);

    int tid = threadIdx.x, lane = tid & 31, wid = tid >> 5;
    int gid = lane >> 2, tig = lane & 3;
    int wm = (wid & 1) * 64, wn = (wid >> 1) * 32;

    __nv_bfloat16* T = (__nv_bfloat16*)sdyn;  // [128 n][136 c-pitch]
#pragma unroll
    for (int mi = 0; mi < 4; mi++) {
        int cl = wm + mi * 16 + gid;
#pragma unroll
        for (int ni = 0; ni < 4; ni++) {
            int nl = wn + ni * 8 + tig * 2;
            float inv0 = 1.0f / g_rowsum[(size_t)b * NN + nB + nl];
            float inv1 = 1.0f / g_rowsum[(size_t)b * NN + nB + nl + 1];
            T[nl * 136 + cl] = __float2bfloat16_rn(acc[mi][ni][0] * inv0);
            T[(nl + 1) * 136 + cl] = __float2bfloat16_rn(acc[mi][ni][1] * inv1);
            T[nl * 136 + cl + 8] = __float2bfloat16_rn(acc[mi][ni][2] * inv0);
            T[(nl + 1) * 136 + cl + 8] = __float2bfloat16_rn(acc[mi][ni][3] * inv1);
        }
    }
    __syncthreads();
    {
        int nl = tid >> 1, h = tid & 1;
        __nv_bfloat16* drow = g_attt + ((size_t)b * NN + nB + nl) * CC + cB + h * 64;
        const __nv_bfloat16* srow = T + nl * 136 + h * 64;
#pragma unroll
        for (int j = 0; j < 8; j++)
            *(uint4*)(drow + j * 8) = *(const uint4*)(srow + j * 8);
    }
}

// ============================================================
// Kernel 8: proj + bias + residual.
// ============================================================
__global__ __launch_bounds__(256, 2) void proj_bf_kernel(const float* __restrict__ x,
                                                         const float* __restrict__ pb,
                                                         float* __restrict__ out) {
    extern __shared__ char sdyn[];
    uint32_t sbase = smem_u32(sdyn);
    int b = blockIdx.z;
    int o_blk = blockIdx.y * 128, n_blk = blockIdx.x * 128;
    const __nv_bfloat16* A = g_pwf + (size_t)o_blk * CC;
    const __nv_bfloat16* B = g_attt + (size_t)b * NN * CC + (size_t)n_blk * CC;

    float acc[4][4][4] = {};
    bf_gemm(A, CC, B, CC, CC / 64, sdyn, sbase, acc);

    int tid = threadIdx.x, lane = tid & 31, wid = tid >> 5;
    int gid = lane >> 2, tig = lane & 3;
    int wm = (wid & 1) * 64, wn = (wid >> 1) * 32;
#pragma unroll
    for (int mi = 0; mi < 4; mi++) {
        int o = o_blk + wm + mi * 16 + gid;
        float bv0 = pb[o], bv1 = pb[o + 8];
        size_t base0 = ((size_t)b * CC + o) * NN + n_blk;
        size_t base1 = base0 + (size_t)8 * NN;
#pragma unroll
        for (int ni = 0; ni < 4; ni++) {
            int cb = wn + ni * 8 + tig * 2;
            float2 x0 = *(const float2*)(x + base0 + cb);
            float2 x1 = *(const float2*)(x + base1 + cb);
            *(float2*)(out + base0 + cb) =
                make_float2(acc[mi][ni][0] + bv0 + x0.x, acc[mi][ni][1] + bv0 + x0.y);
            *(float2*)(out + base1 + cb) =
                make_float2(acc[mi][ni][2] + bv1 + x1.x, acc[mi][ni][3] + bv1 + x1.y);
        }
    }
}

// ============================================================
// launch
// ============================================================
extern "C" void kernel_launch(void* const* d_in, const int* in_sizes, int n_in,
                              void* d_out, int out_size) {
    const float* x     = (const float*)d_in[0];
    const float* gamma = (const float*)d_in[1];
    const float* beta  = (const float*)d_in[2];
    const float* q_w   = (const float*)d_in[3];
    const float* q_b   = (const float*)d_in[4];
    const float* k_w   = (const float*)d_in[5];
    const float* k_b   = (const float*)d_in[6];
    const float* p_w   = (const float*)d_in[7];
    const float* p_b   = (const float*)d_in[8];
    float* out = (float*)d_out;

    (void)in_sizes; (void)n_in; (void)out_size;

    cudaFuncSetAttribute(qk_bf_kernel, cudaFuncAttributeMaxDynamicSharedMemorySize, SMEM_DYN);
    cudaFuncSetAttribute(scores_bf_kernel, cudaFuncAttributeMaxDynamicSharedMemorySize, SMEM_DYN);
    cudaFuncSetAttribute(av_bf_kernel, cudaFuncAttributeMaxDynamicSharedMemorySize, SMEM_DYN);
    cudaFuncSetAttribute(proj_bf_kernel, cudaFuncAttributeMaxDynamicSharedMemorySize, SMEM_DYN);

    gn_stats_kernel<<<dim3(BATCH, GG), 256>>>(x);
    fold_kernel<<<dim3(BATCH, 4), 256>>>(q_w, q_b, k_w, k_b, p_w, gamma, beta);
    xt_kernel<<<dim3(NN / 64, CC / 64, BATCH), 256>>>(x);

    qk_bf_kernel<<<dim3(NN / 128, CC / 128, BATCH * 2), 256, SMEM_DYN>>>();
    scores_bf_kernel<<<dim3(NN / (128 * MT), NN / 128, BATCH), 256, SMEM_DYN>>>();
    rowsum_reduce_kernel<<<(BATCH * NN) / 256, 256>>>();
    av_bf_kernel<<<dim3(NN / 128, CC / 128, BATCH), 256, SMEM_DYN>>>();
    proj_bf_kernel<<<dim3(NN / 128, CC / 128, BATCH), 256, SMEM_DYN>>>(x, p_b, out);
}

// round 17
// speedup vs baseline: 1.0137x; 1.0137x over previous
#include <cuda_runtime.h>
#include <cuda_bf16.h>
#include <math.h>
#include <stdint.h>

#define BATCH 8
#define CC 512
#define NN 4096
#define GG 32
#define CPG 16

// ---- scratch (static device globals; allowed by harness rules) ----
__device__ __nv_bfloat16 g_qt[(size_t)BATCH * NN * CC];    // q_t  [b][n][c]
__device__ __nv_bfloat16 g_ktb[(size_t)BATCH * NN * CC];   // k_t  [b][m][c]
__device__ __nv_bfloat16 g_kb[(size_t)BATCH * CC * NN];    // k    [b][c][m]
__device__ __nv_bfloat16 g_xt[(size_t)BATCH * NN * CC];    // x_t  [b][n][c]
__device__ __nv_bfloat16 g_attt[(size_t)BATCH * NN * CC];  // att_t[b][n][c]
__device__ __nv_bfloat16 g_s[(size_t)BATCH * NN * NN];     // E = exp(S) [b][n][m]
__device__ float g_psum[(size_t)BATCH * NN * 32];          // per-mblock row partials
__device__ float g_rowsum[(size_t)BATCH * NN];             // sum_m exp(S)
__device__ __nv_bfloat16 g_qwf[(size_t)BATCH * CC * CC];
__device__ __nv_bfloat16 g_kwf[(size_t)BATCH * CC * CC];
__device__ __nv_bfloat16 g_pwf[(size_t)CC * CC];
__device__ float g_stats[BATCH * GG * 2];
__device__ float g_qbf[BATCH * CC];
__device__ float g_kbf[BATCH * CC];

// ============================================================
// helpers
// ============================================================
__device__ __forceinline__ unsigned packbf(float x, float y) {
    __nv_bfloat162 h = __float22bfloat162_rn(make_float2(x, y));
    return *reinterpret_cast<unsigned*>(&h);
}

__device__ __forceinline__ void mma16(float* c, unsigned a0, unsigned a1, unsigned a2, unsigned a3,
                                      unsigned b0, unsigned b1) {
    asm volatile(
        "mma.sync.aligned.m16n8k16.row.col.f32.bf16.bf16.f32 "
        "{%0,%1,%2,%3},{%4,%5,%6,%7},{%8,%9},{%0,%1,%2,%3};"
        : "+f"(c[0]), "+f"(c[1]), "+f"(c[2]), "+f"(c[3])
        : "r"(a0), "r"(a1), "r"(a2), "r"(a3), "r"(b0), "r"(b1));
}

#define LDSM4(r0, r1, r2, r3, addr) \
    asm volatile("ldmatrix.sync.aligned.m8n8.x4.shared.b16 {%0,%1,%2,%3}, [%4];" \
                 : "=r"(r0), "=r"(r1), "=r"(r2), "=r"(r3) : "r"(addr))

__device__ __forceinline__ void cp16(void* smem_dst, const void* gsrc) {
    unsigned s = (unsigned)__cvta_generic_to_shared(smem_dst);
    asm volatile("cp.async.cg.shared.global [%0], [%1], 16;" :: "r"(s), "l"(gsrc));
}
#define CP_COMMIT asm volatile("cp.async.commit_group;")
#define CP_WAIT1 asm volatile("cp.async.wait_group 1;")
#define CP_WAIT0 asm volatile("cp.async.wait_group 0;")

__device__ __forceinline__ uint32_t smem_u32(const void* p) {
    uint32_t a;
    asm("{ .reg .u64 t; cvta.to.shared.u64 t, %1; cvt.u32.u64 %0, t; }" : "=r"(a) : "l"(p));
    return a;
}

// ============================================================
// bf16 GEMM mainloop (128x128 tile, 8 warps 64x32, 2-stage).
// smem stage s at s*36864: A [128][72 bf16] (144 B pitch), B at +18432.
// ============================================================
#define STAGE_B 36864
#define SMEM_DYN (2 * STAGE_B)

__device__ __forceinline__ void bf_gemm(const __nv_bfloat16* A, size_t ldA,
                                        const __nv_bfloat16* B, size_t ldB,
                                        int NCH, char* sdyn, uint32_t sbase,
                                        float acc[4][4][4]) {
    int tid = threadIdx.x, lane = tid & 31, wid = tid >> 5;
    int wm = (wid & 1) * 64, wn = (wid >> 1) * 32;
    int lrow = tid >> 3, lseg = tid & 7;

    uint32_t a_off = (uint32_t)(((lane & 7) + ((lane >> 3) & 1) * 8) * 144 + (lane >> 4) * 16);
    uint32_t b_off = (uint32_t)((((lane >> 4) << 3) + (lane & 7)) * 144 + ((lane >> 3) & 1) * 16);

#define BF_LOAD(st, c0)                                                                   \
    {                                                                                     \
        _Pragma("unroll") for (int r = 0; r < 4; r++) {                                   \
            int rr = lrow + r * 32;                                                       \
            cp16(sdyn + (st) * STAGE_B + rr * 144 + lseg * 16,                            \
                 A + (size_t)rr * ldA + (c0) + lseg * 8);                                 \
            cp16(sdyn + (st) * STAGE_B + 18432 + rr * 144 + lseg * 16,                    \
                 B + (size_t)rr * ldB + (c0) + lseg * 8);                                 \
        }                                                                                 \
    }

    BF_LOAD(0, 0);
    CP_COMMIT;
    for (int it = 0; it < NCH; it++) {
        if (it + 1 < NCH) {
            BF_LOAD((it + 1) & 1, (it + 1) * 64);
            CP_COMMIT;
            CP_WAIT1;
        } else {
            CP_WAIT0;
        }
        __syncthreads();
        uint32_t sA = sbase + (it & 1) * STAGE_B + wm * 144;
        uint32_t sB = sbase + (it & 1) * STAGE_B + 18432 + wn * 144;
#pragma unroll
        for (int ks = 0; ks < 4; ks++) {
            unsigned a[4][4], bb[2][4];
#pragma unroll
            for (int mi = 0; mi < 4; mi++)
                LDSM4(a[mi][0], a[mi][1], a[mi][2], a[mi][3],
                      sA + mi * (16 * 144) + ks * 32 + a_off);
#pragma unroll
            for (int np = 0; np < 2; np++)
                LDSM4(bb[np][0], bb[np][1], bb[np][2], bb[np][3],
                      sB + np * (16 * 144) + ks * 32 + b_off);
#pragma unroll
            for (int mi = 0; mi < 4; mi++) {
                mma16(acc[mi][0], a[mi][0], a[mi][1], a[mi][2], a[mi][3], bb[0][0], bb[0][1]);
                mma16(acc[mi][1], a[mi][0], a[mi][1], a[mi][2], a[mi][3], bb[0][2], bb[0][3]);
                mma16(acc[mi][2], a[mi][0], a[mi][1], a[mi][2], a[mi][3], bb[1][0], bb[1][1]);
                mma16(acc[mi][3], a[mi][0], a[mi][1], a[mi][2], a[mi][3], bb[1][2], bb[1][3]);
            }
        }
        __syncthreads();
    }
#undef BF_LOAD
}

// ============================================================
// Kernel 1: GroupNorm statistics
// ============================================================
__global__ void gn_stats_kernel(const float* __restrict__ x) {
    int b = blockIdx.x, g = blockIdx.y;
    const float4* xp = (const float4*)(x + ((size_t)(b * CC) + g * CPG) * NN);
    float s = 0.f, s2 = 0.f;
    for (int i = threadIdx.x; i < CPG * NN / 4; i += 256) {
        float4 v = xp[i];
        s += v.x + v.y + v.z + v.w;
        s2 += v.x * v.x + v.y * v.y + v.z * v.z + v.w * v.w;
    }
    __shared__ float sh[256], sh2[256];
    sh[threadIdx.x] = s;
    sh2[threadIdx.x] = s2;
    __syncthreads();
    for (int off = 128; off > 0; off >>= 1) {
        if (threadIdx.x < off) {
            sh[threadIdx.x] += sh[threadIdx.x + off];
            sh2[threadIdx.x] += sh2[threadIdx.x + off];
        }
        __syncthreads();
    }
    if (threadIdx.x == 0) {
        const float inv = 1.f / (float)(CPG * NN);
        float mu = sh[0] * inv;
        float var = sh2[0] * inv - mu * mu;
        g_stats[(b * GG + g) * 2 + 0] = mu;
        g_stats[(b * GG + g) * 2 + 1] = rsqrtf(var + 1e-6f);
    }
}

// ============================================================
// Kernel 2: fold GN + softmax scale into bf16 weights + fp32 biases
// ============================================================
__global__ void fold_kernel(const float* __restrict__ qw, const float* __restrict__ qb,
                            const float* __restrict__ kw, const float* __restrict__ kb,
                            const float* __restrict__ pw,
                            const float* __restrict__ gamma, const float* __restrict__ beta) {
    int b = blockIdx.x, o0 = blockIdx.y * 128;
    __shared__ float ga[CC], be[CC];
    for (int c = threadIdx.x; c < CC; c += 256) {
        int g = c >> 4;
        float mu = g_stats[(b * GG + g) * 2 + 0];
        float rstd = g_stats[(b * GG + g) * 2 + 1];
        float gg = gamma[c] * rstd;
        ga[c] = gg;
        be[c] = beta[c] - mu * gg;
    }
    __syncthreads();
    const float s = rsqrtf((float)CC);
    for (int idx = threadIdx.x; idx < 128 * CC; idx += 256) {
        int o = o0 + (idx >> 9), c = idx & (CC - 1);
        g_qwf[((size_t)b * CC + o) * CC + c] = __float2bfloat16_rn(qw[(size_t)o * CC + c] * ga[c] * s);
        g_kwf[((size_t)b * CC + o) * CC + c] = __float2bfloat16_rn(kw[(size_t)o * CC + c] * ga[c]);
    }
    {
        int o = o0 + (threadIdx.x >> 1);
        int h = (threadIdx.x & 1) * 256;
        float sq = 0.f, sk = 0.f;
        for (int c = h; c < h + 256; c++) {
            sq += qw[(size_t)o * CC + c] * be[c];
            sk += kw[(size_t)o * CC + c] * be[c];
        }
        sq += __shfl_xor_sync(0xffffffffu, sq, 1);
        sk += __shfl_xor_sync(0xffffffffu, sk, 1);
        if ((threadIdx.x & 1) == 0) {
            g_qbf[b * CC + o] = (qb[o] + sq) * s;
            g_kbf[b * CC + o] = kb[o] + sk;
        }
    }
    if (b == 0) {
        for (int idx = threadIdx.x; idx < 128 * CC; idx += 256) {
            int o = o0 + (idx >> 9), c = idx & (CC - 1);
            g_pwf[(size_t)o * CC + c] = __float2bfloat16_rn(pw[(size_t)o * CC + c]);
        }
    }
}

// ============================================================
// Kernel 3: x[c][n] fp32 -> x_t[n][c] bf16 (tiled transpose)
// ============================================================
__global__ void xt_kernel(const float* __restrict__ x) {
    __shared__ float ts[32][33];
    int b = blockIdx.z;
    int n0 = blockIdx.x * 32, c0 = blockIdx.y * 32;
    int tx = threadIdx.x, ty = threadIdx.y;
#pragma unroll
    for (int r = 0; r < 4; r++) {
        int c = c0 + ty + r * 8;
        ts[tx][ty + r * 8] = x[((size_t)b * CC + c) * NN + n0 + tx];
    }
    __syncthreads();
#pragma unroll
    for (int r = 0; r < 4; r++) {
        int n = n0 + ty + r * 8;
        g_xt[((size_t)b * NN + n) * CC + c0 + tx] = __float2bfloat16_rn(ts[ty + r * 8][tx]);
    }
}

// ============================================================
// Kernel 4: q/k projection + transposed epilogues.
// ============================================================
__global__ __launch_bounds__(256, 2) void qk_bf_kernel() {
    extern __shared__ char sdyn[];
    uint32_t sbase = smem_u32(sdyn);
    int b = blockIdx.z >> 1, which = blockIdx.z & 1;
    int o_blk = blockIdx.y * 128, n_blk = blockIdx.x * 128;
    const __nv_bfloat16* A = (which ? g_kwf : g_qwf) + (size_t)b * CC * CC + (size_t)o_blk * CC;
    const __nv_bfloat16* B = g_xt + (size_t)b * NN * CC + (size_t)n_blk * CC;
    const float* bias = (which ? g_kbf : g_qbf) + b * CC;

    float acc[4][4][4] = {};
    bf_gemm(A, CC, B, CC, CC / 64, sdyn, sbase, acc);

    int tid = threadIdx.x, lane = tid & 31, wid = tid >> 5;
    int gid = lane >> 2, tig = lane & 3;
    int wm = (wid & 1) * 64, wn = (wid >> 1) * 32;

    __nv_bfloat16* T = (__nv_bfloat16*)sdyn;  // [128 n][136 o-pitch]
#pragma unroll
    for (int mi = 0; mi < 4; mi++) {
        int ol = wm + mi * 16 + gid;
        float bv0 = bias[o_blk + ol], bv1 = bias[o_blk + ol + 8];
#pragma unroll
        for (int ni = 0; ni < 4; ni++) {
            int nl = wn + ni * 8 + tig * 2;
            __nv_bfloat16 b00 = __float2bfloat16_rn(acc[mi][ni][0] + bv0);
            __nv_bfloat16 b01 = __float2bfloat16_rn(acc[mi][ni][1] + bv0);
            __nv_bfloat16 b10 = __float2bfloat16_rn(acc[mi][ni][2] + bv1);
            __nv_bfloat16 b11 = __float2bfloat16_rn(acc[mi][ni][3] + bv1);
            if (which) {
                __nv_bfloat162 p0; p0.x = b00; p0.y = b01;
                __nv_bfloat162 p1; p1.x = b10; p1.y = b11;
                *(__nv_bfloat162*)&g_kb[((size_t)b * CC + o_blk + ol) * NN + n_blk + nl] = p0;
                *(__nv_bfloat162*)&g_kb[((size_t)b * CC + o_blk + ol + 8) * NN + n_blk + nl] = p1;
            }
            T[nl * 136 + ol] = b00;
            T[(nl + 1) * 136 + ol] = b01;
            T[nl * 136 + ol + 8] = b10;
            T[(nl + 1) * 136 + ol + 8] = b11;
        }
    }
    __syncthreads();
    {
        __nv_bfloat16* dst = (which ? g_ktb : g_qt) + (size_t)b * NN * CC;
        int nl = tid >> 1, h = tid & 1;
        __nv_bfloat16* drow = dst + (size_t)(n_blk + nl) * CC + o_blk + h * 64;
        const __nv_bfloat16* srow = T + nl * 136 + h * 64;
#pragma unroll
        for (int j = 0; j < 8; j++)
            *(uint4*)(drow + j * 8) = *(const uint4*)(srow + j * 8);
    }
}

// ============================================================
// Kernel 5: scores + fused exp. E[n][m] = exp(S[n][m]) (bf16 out),
// per-block row partial sums -> g_psum (smem atomics, no global atomics).
// ============================================================
__global__ __launch_bounds__(256, 2) void scores_bf_kernel() {
    extern __shared__ char sdyn[];
    uint32_t sbase = smem_u32(sdyn);
    int b = blockIdx.z;
    int nB = blockIdx.y * 128, mB = blockIdx.x * 128;
    int mblk = blockIdx.x;
    const __nv_bfloat16* A = g_qt + (size_t)b * NN * CC + (size_t)nB * CC;
    const __nv_bfloat16* B = g_ktb + (size_t)b * NN * CC + (size_t)mB * CC;

    float acc[4][4][4] = {};
    bf_gemm(A, CC, B, CC, CC / 64, sdyn, sbase, acc);

    int tid = threadIdx.x, lane = tid & 31, wid = tid >> 5;
    int gid = lane >> 2, tig = lane & 3;
    int wm = (wid & 1) * 64, wn = (wid >> 1) * 32;

    float* srow = (float*)sdyn;  // 128 row partials (stage smem now dead)
    if (tid < 128) srow[tid] = 0.f;
    __syncthreads();

#pragma unroll
    for (int mi = 0; mi < 4; mi++) {
        int rloc = wm + mi * 16 + gid;
        int qrow = nB + rloc;
        __nv_bfloat16* p0 = g_s + ((size_t)b * NN + qrow) * NN + mB;
        __nv_bfloat16* p1 = p0 + (size_t)8 * NN;
        float s0 = 0.f, s1 = 0.f;
#pragma unroll
        for (int ni = 0; ni < 4; ni++) {
            int cb = wn + ni * 8 + tig * 2;
            float e0 = __expf(acc[mi][ni][0]);
            float e1 = __expf(acc[mi][ni][1]);
            float e2 = __expf(acc[mi][ni][2]);
            float e3 = __expf(acc[mi][ni][3]);
            s0 += e0 + e1;
            s1 += e2 + e3;
            *(unsigned*)(p0 + cb) = packbf(e0, e1);
            *(unsigned*)(p1 + cb) = packbf(e2, e3);
        }
        s0 += __shfl_xor_sync(0xffffffffu, s0, 1);
        s0 += __shfl_xor_sync(0xffffffffu, s0, 2);
        s1 += __shfl_xor_sync(0xffffffffu, s1, 1);
        s1 += __shfl_xor_sync(0xffffffffu, s1, 2);
        if (tig == 0) {
            atomicAdd(&srow[rloc], s0);
            atomicAdd(&srow[rloc + 8], s1);
        }
    }
    __syncthreads();
    if (tid < 128)
        g_psum[((size_t)b * NN + nB + tid) * 32 + mblk] = srow[tid];
}

// ============================================================
// Kernel 6: rowsum reduce. g_rowsum[row] = sum of 32 partials.
// ============================================================
__global__ void rowsum_reduce_kernel() {
    size_t row = (size_t)blockIdx.x * 256 + threadIdx.x;
    const float* p = g_psum + row * 32;
    float s = 0.f;
#pragma unroll
    for (int i = 0; i < 32; i++) s += p[i];
    g_rowsum[row] = s;
}

// ============================================================
// Kernel 7: AV + normalization. att_t[n][c] = (k·E^T)[c][n] / rowsum[n]
// rowsum inverses hoisted: 8 loads + 8 divides per thread total.
// ============================================================
__global__ __launch_bounds__(256, 2) void av_bf_kernel() {
    extern __shared__ char sdyn[];
    uint32_t sbase = smem_u32(sdyn);
    int b = blockIdx.z;
    int cB = blockIdx.y * 128, nB = blockIdx.x * 128;
    const __nv_bfloat16* A = g_kb + (size_t)b * CC * NN + (size_t)cB * NN;
    const __nv_bfloat16* B = g_s + (size_t)b * NN * NN + (size_t)nB * NN;

    float acc[4][4][4] = {};
    bf_gemm(A, NN, B, NN, NN / 64, sdyn, sbase, acc);

    int tid = threadIdx.x, lane = tid & 31, wid = tid >> 5;
    int gid = lane >> 2, tig = lane & 3;
    int wm = (wid & 1) * 64, wn = (wid >> 1) * 32;

    // hoist the 8 distinct rowsum inverses this thread needs
    float inv[4][2];
#pragma unroll
    for (int ni = 0; ni < 4; ni++) {
        int nl = wn + ni * 8 + tig * 2;
        inv[ni][0] = 1.0f / g_rowsum[(size_t)b * NN + nB + nl];
        inv[ni][1] = 1.0f / g_rowsum[(size_t)b * NN + nB + nl + 1];
    }

    __nv_bfloat16* T = (__nv_bfloat16*)sdyn;  // [128 n][136 c-pitch]
#pragma unroll
    for (int mi = 0; mi < 4; mi++) {
        int cl = wm + mi * 16 + gid;
#pragma unroll
        for (int ni = 0; ni < 4; ni++) {
            int nl = wn + ni * 8 + tig * 2;
            T[nl * 136 + cl] = __float2bfloat16_rn(acc[mi][ni][0] * inv[ni][0]);
            T[(nl + 1) * 136 + cl] = __float2bfloat16_rn(acc[mi][ni][1] * inv[ni][1]);
            T[nl * 136 + cl + 8] = __float2bfloat16_rn(acc[mi][ni][2] * inv[ni][0]);
            T[(nl + 1) * 136 + cl + 8] = __float2bfloat16_rn(acc[mi][ni][3] * inv[ni][1]);
        }
    }
    __syncthreads();
    {
        int nl = tid >> 1, h = tid & 1;
        __nv_bfloat16* drow = g_attt + ((size_t)b * NN + nB + nl) * CC + cB + h * 64;
        const __nv_bfloat16* srow = T + nl * 136 + h * 64;
#pragma unroll
        for (int j = 0; j < 8; j++)
            *(uint4*)(drow + j * 8) = *(const uint4*)(srow + j * 8);
    }
}

// ============================================================
// Kernel 8: proj + bias + residual.
// ============================================================
__global__ __launch_bounds__(256, 2) void proj_bf_kernel(const float* __restrict__ x,
                                                         const float* __restrict__ pb,
                                                         float* __restrict__ out) {
    extern __shared__ char sdyn[];
    uint32_t sbase = smem_u32(sdyn);
    int b = blockIdx.z;
    int o_blk = blockIdx.y * 128, n_blk = blockIdx.x * 128;
    const __nv_bfloat16* A = g_pwf + (size_t)o_blk * CC;
    const __nv_bfloat16* B = g_attt + (size_t)b * NN * CC + (size_t)n_blk * CC;

    float acc[4][4][4] = {};
    bf_gemm(A, CC, B, CC, CC / 64, sdyn, sbase, acc);

    int tid = threadIdx.x, lane = tid & 31, wid = tid >> 5;
    int gid = lane >> 2, tig = lane & 3;
    int wm = (wid & 1) * 64, wn = (wid >> 1) * 32;
#pragma unroll
    for (int mi = 0; mi < 4; mi++) {
        int o = o_blk + wm + mi * 16 + gid;
        float bv0 = pb[o], bv1 = pb[o + 8];
        size_t base0 = ((size_t)b * CC + o) * NN + n_blk;
        size_t base1 = base0 + (size_t)8 * NN;
#pragma unroll
        for (int ni = 0; ni < 4; ni++) {
            int cb = wn + ni * 8 + tig * 2;
            float2 x0 = *(const float2*)(x + base0 + cb);
            float2 x1 = *(const float2*)(x + base1 + cb);
            *(float2*)(out + base0 + cb) =
                make_float2(acc[mi][ni][0] + bv0 + x0.x, acc[mi][ni][1] + bv0 + x0.y);
            *(float2*)(out + base1 + cb) =
                make_float2(acc[mi][ni][2] + bv1 + x1.x, acc[mi][ni][3] + bv1 + x1.y);
        }
    }
}

// ============================================================
// launch
// ============================================================
extern "C" void kernel_launch(void* const* d_in, const int* in_sizes, int n_in,
                              void* d_out, int out_size) {
    const float* x     = (const float*)d_in[0];
    const float* gamma = (const float*)d_in[1];
    const float* beta  = (const float*)d_in[2];
    const float* q_w   = (const float*)d_in[3];
    const float* q_b   = (const float*)d_in[4];
    const float* k_w   = (const float*)d_in[5];
    const float* k_b   = (const float*)d_in[6];
    const float* p_w   = (const float*)d_in[7];
    const float* p_b   = (const float*)d_in[8];
    float* out = (float*)d_out;

    (void)in_sizes; (void)n_in; (void)out_size;

    cudaFuncSetAttribute(qk_bf_kernel, cudaFuncAttributeMaxDynamicSharedMemorySize, SMEM_DYN);
    cudaFuncSetAttribute(scores_bf_kernel, cudaFuncAttributeMaxDynamicSharedMemorySize, SMEM_DYN);
    cudaFuncSetAttribute(av_bf_kernel, cudaFuncAttributeMaxDynamicSharedMemorySize, SMEM_DYN);
    cudaFuncSetAttribute(proj_bf_kernel, cudaFuncAttributeMaxDynamicSharedMemorySize, SMEM_DYN);

    gn_stats_kernel<<<dim3(BATCH, GG), 256>>>(x);
    fold_kernel<<<dim3(BATCH, 4), 256>>>(q_w, q_b, k_w, k_b, p_w, gamma, beta);
    xt_kernel<<<dim3(NN / 32, CC / 32, BATCH), dim3(32, 8)>>>(x);

    qk_bf_kernel<<<dim3(NN / 128, CC / 128, BATCH * 2), 256, SMEM_DYN>>>();
    scores_bf_kernel<<<dim3(NN / 128, NN / 128, BATCH), 256, SMEM_DYN>>>();
    rowsum_reduce_kernel<<<(BATCH * NN) / 256, 256>>>();
    av_bf_kernel<<<dim3(NN / 128, CC / 128, BATCH), 256, SMEM_DYN>>>();
    proj_bf_kernel<<<dim3(NN / 128, CC / 128, BATCH), 256, SMEM_DYN>>>(x, p_b, out);
}